// round 2
// baseline (speedup 1.0000x reference)
#include <cuda_runtime.h>
#include <math.h>

typedef unsigned long long u64;

#define B_ROWS 16384   // b*n
#define TOK 16
#define CIN 128
#define CFF 512
#define COUT 128
#define MT 64          // rows per CTA
#define TPB 256

// -------- scratch (static __device__, allocation-free) --------
__device__ float g_xp[(size_t)TOK * B_ROWS * CIN];    // [t][row][c]
__device__ float g_yp[(size_t)TOK * B_ROWS * COUT];   // [t][row][o]
__device__ float g_w1p[(size_t)TOK * CFF * CIN];      // [t][o][c]
__device__ float g_w2p[(size_t)TOK * COUT * CFF];     // [t][o][k]

// -------- f32x2 packed FMA helpers (sm_100+ PTX) --------
__device__ __forceinline__ u64 pack2(float lo, float hi) {
    u64 r; asm("mov.b64 %0, {%1, %2};" : "=l"(r) : "f"(lo), "f"(hi)); return r;
}
__device__ __forceinline__ void unpack2(u64 v, float& lo, float& hi) {
    asm("mov.b64 {%0, %1}, %2;" : "=f"(lo), "=f"(hi) : "l"(v));
}
__device__ __forceinline__ u64 fma2(u64 a, u64 b, u64 c) {
    u64 d; asm("fma.rn.f32x2 %0, %1, %2, %3;" : "=l"(d) : "l"(a), "l"(b), "l"(c)); return d;
}

__device__ __forceinline__ float gelu_exact(float x) {
    return 0.5f * x * (1.0f + erff(x * 0.70710678118654752f));
}

// ============================================================
// permute x[row, c*16+t] -> xp[t][row][c]
// ============================================================
__global__ void permute_x_kernel(const float* __restrict__ x) {
    __shared__ float s[128 * 17];
    const int row = blockIdx.x;
    const float* src = x + (size_t)row * 2048;
    for (int i = threadIdx.x; i < 2048; i += TPB) {
        int c = i >> 4, t = i & 15;
        s[c * 17 + t] = src[i];
    }
    __syncthreads();
    for (int i = threadIdx.x; i < 2048; i += TPB) {
        int t = i >> 7, c = i & 127;
        g_xp[((size_t)t * B_ROWS + row) * CIN + c] = s[c * 17 + t];
    }
}

// w1[o, c, t] (o*128+c)*16+t  -> w1p[t][o*128+c]
__global__ void permute_w1_kernel(const float* __restrict__ w) {
    int idx = blockIdx.x * blockDim.x + threadIdx.x;   // 0 .. 512*128-1
    if (idx >= CFF * CIN) return;
    const float* src = w + (size_t)idx * TOK;
    float v[16];
    float4 a0 = *(const float4*)(src + 0);
    float4 a1 = *(const float4*)(src + 4);
    float4 a2 = *(const float4*)(src + 8);
    float4 a3 = *(const float4*)(src + 12);
    v[0]=a0.x; v[1]=a0.y; v[2]=a0.z; v[3]=a0.w;
    v[4]=a1.x; v[5]=a1.y; v[6]=a1.z; v[7]=a1.w;
    v[8]=a2.x; v[9]=a2.y; v[10]=a2.z; v[11]=a2.w;
    v[12]=a3.x; v[13]=a3.y; v[14]=a3.z; v[15]=a3.w;
#pragma unroll
    for (int t = 0; t < TOK; t++)
        g_w1p[(size_t)t * CFF * CIN + idx] = v[t];
}

// w2[o, k, t] (o*512+k)*16+t -> w2p[t][o*512+k]
__global__ void permute_w2_kernel(const float* __restrict__ w) {
    int idx = blockIdx.x * blockDim.x + threadIdx.x;   // 0 .. 128*512-1
    if (idx >= COUT * CFF) return;
    const float* src = w + (size_t)idx * TOK;
    float v[16];
    float4 a0 = *(const float4*)(src + 0);
    float4 a1 = *(const float4*)(src + 4);
    float4 a2 = *(const float4*)(src + 8);
    float4 a3 = *(const float4*)(src + 12);
    v[0]=a0.x; v[1]=a0.y; v[2]=a0.z; v[3]=a0.w;
    v[4]=a1.x; v[5]=a1.y; v[6]=a1.z; v[7]=a1.w;
    v[8]=a2.x; v[9]=a2.y; v[10]=a2.z; v[11]=a2.w;
    v[12]=a3.x; v[13]=a3.y; v[14]=a3.z; v[15]=a3.w;
#pragma unroll
    for (int t = 0; t < TOK; t++)
        g_w2p[(size_t)t * COUT * CFF + idx] = v[t];
}

// yp[t][row][o] -> y[row, o*16+t]
__global__ void permute_y_kernel(float* __restrict__ y) {
    __shared__ float s[128 * 17];
    const int row = blockIdx.x;
    for (int i = threadIdx.x; i < 2048; i += TPB) {
        int t = i >> 7, o = i & 127;
        s[o * 17 + t] = g_yp[((size_t)t * B_ROWS + row) * COUT + o];
    }
    __syncthreads();
    float* dst = y + (size_t)row * 2048;
    for (int i = threadIdx.x; i < 2048; i += TPB) {
        int o = i >> 4, t = i & 15;
        dst[i] = s[o * 17 + t];
    }
}

// ============================================================
// fused FFN main kernel: per (t, 64-row tile)
//   H = gelu(X @ W1^T);  Y = H @ W2^T     (all K-major)
// smem: Xs 32KB | Hs 128KB | Ws 2x16KB   => 192KB dynamic
// ============================================================
__global__ void __launch_bounds__(TPB, 1) ffn_main_kernel() {
    extern __shared__ float smem[];
    float* Xs = smem;                    // 64*128   = 8192 floats
    float* Hs = smem + 8192;             // 64*512   = 32768 floats
    float* Ws = smem + 8192 + 32768;     // 2 * 4096 floats

    const int bid = blockIdx.x;
    const int t = bid & 15;              // t-adjacent CTAs share x sectors/L2
    const int m0 = (bid >> 4) * MT;
    const int tid = threadIdx.x;
    const int ty = tid >> 5;             // 0..7  (row group, == warp id)
    const int tx = tid & 31;             // lane

    const float* __restrict__ xp = g_xp + ((size_t)t * B_ROWS + m0) * CIN;
    const float* __restrict__ w1 = g_w1p + (size_t)t * CFF * CIN;
    const float* __restrict__ w2 = g_w2p + (size_t)t * COUT * CFF;
    float* __restrict__ yp = g_yp + ((size_t)t * B_ROWS + m0) * COUT;

    // ---- load X tile [64 x 128], fully coalesced ----
    {
        const float4* src = (const float4*)xp;
        float4* dst = (float4*)Xs;
#pragma unroll
        for (int i = 0; i < 8; i++) dst[i * TPB + tid] = src[i * TPB + tid];
    }

    // ================= GEMM1 + GELU =================
    // two N-halves of 256 columns; thread tile 8 rows x 4 f32x2-pairs
    for (int nh = 0; nh < 2; nh++) {
        __syncthreads();   // Xs ready (nh=0); Ws free to reuse (nh=1)
        u64 acc[8][4];
#pragma unroll
        for (int i = 0; i < 8; i++)
#pragma unroll
            for (int g = 0; g < 4; g++) acc[i][g] = 0ull;

        // each thread stages weight row n = nh*256 + tid, k-chunks of 16
        const float* wsrc = w1 + ((size_t)(nh * 256 + tid)) * CIN;
        float4 pre[4];
#pragma unroll
        for (int q = 0; q < 4; q++) pre[q] = *(const float4*)(wsrc + q * 4);
        {
            float* Wb = Ws;  // buf 0
#pragma unroll
            for (int q = 0; q < 4; q++) {
                Wb[(q * 4 + 0) * 256 + tid] = pre[q].x;
                Wb[(q * 4 + 1) * 256 + tid] = pre[q].y;
                Wb[(q * 4 + 2) * 256 + tid] = pre[q].z;
                Wb[(q * 4 + 3) * 256 + tid] = pre[q].w;
            }
        }

        for (int kc = 0; kc < 8; kc++) {
            __syncthreads();
            if (kc < 7) {
#pragma unroll
                for (int q = 0; q < 4; q++)
                    pre[q] = *(const float4*)(wsrc + (kc + 1) * 16 + q * 4);
            }
            const float* Wc = Ws + (kc & 1) * 4096;
#pragma unroll
            for (int k = 0; k < 16; k++) {
                u64 bv[4];
#pragma unroll
                for (int g = 0; g < 4; g++)
                    bv[g] = *(const u64*)(Wc + k * 256 + tx * 2 + g * 64);
#pragma unroll
                for (int i = 0; i < 8; i++) {
                    float a = Xs[(ty * 8 + i) * CIN + kc * 16 + k];  // warp-broadcast
                    u64 av = pack2(a, a);
#pragma unroll
                    for (int g = 0; g < 4; g++)
                        acc[i][g] = fma2(av, bv[g], acc[i][g]);
                }
            }
            if (kc < 7) {
                float* Wb = Ws + ((kc + 1) & 1) * 4096;
#pragma unroll
                for (int q = 0; q < 4; q++) {
                    Wb[(q * 4 + 0) * 256 + tid] = pre[q].x;
                    Wb[(q * 4 + 1) * 256 + tid] = pre[q].y;
                    Wb[(q * 4 + 2) * 256 + tid] = pre[q].z;
                    Wb[(q * 4 + 3) * 256 + tid] = pre[q].w;
                }
            }
        }

        // exact-erf GELU in registers, store H half to smem
#pragma unroll
        for (int i = 0; i < 8; i++) {
#pragma unroll
            for (int g = 0; g < 4; g++) {
                float lo, hi;
                unpack2(acc[i][g], lo, hi);
                lo = gelu_exact(lo);
                hi = gelu_exact(hi);
                *(float2*)&Hs[(ty * 8 + i) * CFF + nh * 256 + tx * 2 + g * 64] =
                    make_float2(lo, hi);
            }
        }
    }
    __syncthreads();   // Hs complete, Ws free

    // ================= GEMM2 =================
    // Y [64 x 128], K = 512 in 32 stages of 16; thread tile 8 rows x 2 pairs
    u64 acc2[8][2];
#pragma unroll
    for (int i = 0; i < 8; i++) { acc2[i][0] = 0ull; acc2[i][1] = 0ull; }

    const int o2 = tid & 127;
    const int ig = tid >> 7;       // 0/1 : which 8-k group this thread stages
    const float* w2src = w2 + (size_t)o2 * CFF + ig * 8;

    float4 p2[2];
#pragma unroll
    for (int q = 0; q < 2; q++) p2[q] = *(const float4*)(w2src + q * 4);
    {
        float* Wb = Ws;
#pragma unroll
        for (int q = 0; q < 2; q++) {
            Wb[(ig * 8 + q * 4 + 0) * 128 + o2] = p2[q].x;
            Wb[(ig * 8 + q * 4 + 1) * 128 + o2] = p2[q].y;
            Wb[(ig * 8 + q * 4 + 2) * 128 + o2] = p2[q].z;
            Wb[(ig * 8 + q * 4 + 3) * 128 + o2] = p2[q].w;
        }
    }

    for (int s = 0; s < 32; s++) {
        __syncthreads();
        if (s < 31) {
#pragma unroll
            for (int q = 0; q < 2; q++)
                p2[q] = *(const float4*)(w2src + (s + 1) * 16 + q * 4);
        }
        const float* Wc = Ws + (s & 1) * 4096;
#pragma unroll
        for (int k = 0; k < 16; k++) {
            u64 bv0 = *(const u64*)(Wc + k * 128 + tx * 2);
            u64 bv1 = *(const u64*)(Wc + k * 128 + tx * 2 + 64);
#pragma unroll
            for (int i = 0; i < 8; i++) {
                float a = Hs[(ty * 8 + i) * CFF + s * 16 + k];  // warp-broadcast
                u64 av = pack2(a, a);
                acc2[i][0] = fma2(av, bv0, acc2[i][0]);
                acc2[i][1] = fma2(av, bv1, acc2[i][1]);
            }
        }
        if (s < 31) {
            float* Wb = Ws + ((s + 1) & 1) * 4096;
#pragma unroll
            for (int q = 0; q < 2; q++) {
                Wb[(ig * 8 + q * 4 + 0) * 128 + o2] = p2[q].x;
                Wb[(ig * 8 + q * 4 + 1) * 128 + o2] = p2[q].y;
                Wb[(ig * 8 + q * 4 + 2) * 128 + o2] = p2[q].z;
                Wb[(ig * 8 + q * 4 + 3) * 128 + o2] = p2[q].w;
            }
        }
    }

    // ---- store Y tile (coalesced into yp) ----
#pragma unroll
    for (int i = 0; i < 8; i++) {
        float lo, hi;
        unpack2(acc2[i][0], lo, hi);
        *(float2*)&yp[(ty * 8 + i) * COUT + tx * 2] = make_float2(lo, hi);
        unpack2(acc2[i][1], lo, hi);
        *(float2*)&yp[(ty * 8 + i) * COUT + tx * 2 + 64] = make_float2(lo, hi);
    }
}

// ============================================================
extern "C" void kernel_launch(void* const* d_in, const int* in_sizes, int n_in,
                              void* d_out, int out_size) {
    const float* x  = (const float*)d_in[0];
    const float* w1 = (const float*)d_in[1];
    const float* w2 = (const float*)d_in[2];
    float* y = (float*)d_out;
    (void)in_sizes; (void)n_in; (void)out_size;

    const size_t smem_bytes = (8192 + 32768 + 2 * 4096) * sizeof(float);  // 196608
    cudaFuncSetAttribute(ffn_main_kernel,
                         cudaFuncAttributeMaxDynamicSharedMemorySize,
                         (int)smem_bytes);

    permute_x_kernel<<<B_ROWS, TPB>>>(x);
    permute_w1_kernel<<<(CFF * CIN) / TPB, TPB>>>(w1);
    permute_w2_kernel<<<(COUT * CFF) / TPB, TPB>>>(w2);
    ffn_main_kernel<<<TOK * (B_ROWS / MT), TPB, smem_bytes>>>();
    permute_y_kernel<<<B_ROWS, TPB>>>(y);
}

// round 5
// speedup vs baseline: 1.7883x; 1.7883x over previous
#include <cuda_runtime.h>
#include <cuda_bf16.h>
#include <math.h>
#include <stdint.h>

#define B_ROWS 16384
#define TOK 16
#define TPB 256

// ---------------- gmem scratch (static, allocation-free) ----------------
__device__ uint32_t g_xh[(size_t)TOK * B_ROWS * 64];   // [t][row][64] bf16x2 (hi)
__device__ uint32_t g_xl[(size_t)TOK * B_ROWS * 64];   // (lo)
__device__ uint32_t g_w1h[TOK * 512 * 64];             // [t][o=512][64] bf16x2
__device__ uint32_t g_w1l[TOK * 512 * 64];
__device__ uint32_t g_w2h[TOK * 128 * 256];            // [t][o=128][256] bf16x2
__device__ uint32_t g_w2l[TOK * 128 * 256];
__device__ float    g_yp[(size_t)TOK * B_ROWS * 128];  // [t][row][o] fp32

// ---------------- helpers ----------------
__device__ __forceinline__ uint32_t smem_to_u32(const void* p) {
    uint32_t a;
    asm("{ .reg .u64 t; cvta.to.shared.u64 t, %1; cvt.u32.u64 %0, t; }"
        : "=r"(a) : "l"(p));
    return a;
}

__device__ __forceinline__ void ldsm4(uint32_t r[4], uint32_t addr) {
    asm volatile("ldmatrix.sync.aligned.m8n8.x4.shared.b16 {%0,%1,%2,%3}, [%4];"
                 : "=r"(r[0]), "=r"(r[1]), "=r"(r[2]), "=r"(r[3]) : "r"(addr));
}

__device__ __forceinline__ void mma_bf16(float c[4], const uint32_t a[4],
                                         uint32_t b0, uint32_t b1) {
    asm volatile(
        "mma.sync.aligned.m16n8k16.row.col.f32.bf16.bf16.f32 "
        "{%0,%1,%2,%3}, {%4,%5,%6,%7}, {%8,%9}, {%0,%1,%2,%3};"
        : "+f"(c[0]), "+f"(c[1]), "+f"(c[2]), "+f"(c[3])
        : "r"(a[0]), "r"(a[1]), "r"(a[2]), "r"(a[3]), "r"(b0), "r"(b1));
}

__device__ __forceinline__ void split2(float f0, float f1, uint32_t& hh, uint32_t& ll) {
    __nv_bfloat16 h0 = __float2bfloat16(f0);
    __nv_bfloat16 h1 = __float2bfloat16(f1);
    float l0 = f0 - __bfloat162float(h0);
    float l1 = f1 - __bfloat162float(h1);
    __nv_bfloat16 m0 = __float2bfloat16(l0);
    __nv_bfloat16 m1 = __float2bfloat16(l1);
    hh = (uint32_t)__bfloat16_as_ushort(h0) | ((uint32_t)__bfloat16_as_ushort(h1) << 16);
    ll = (uint32_t)__bfloat16_as_ushort(m0) | ((uint32_t)__bfloat16_as_ushort(m1) << 16);
}

// exact-erf GELU: 11-term odd Taylor on |x|<=2 (err < 2.5e-6), erff tail
__device__ __forceinline__ float gelu_f(float x) {
    float z = 0.70710678118654752f * x;
    float r;
    if (fabsf(x) <= 2.0f) {
        float u = z * z;
        float p =              1.4807192e-8f;
        p = fmaf(p, u, -1.6365349e-7f);
        p = fmaf(p, u,  1.6462114e-6f);
        p = fmaf(p, u, -1.4925650e-5f);
        p = fmaf(p, u,  1.2055332e-4f);
        p = fmaf(p, u, -8.5483270e-4f);
        p = fmaf(p, u,  5.2239776e-3f);
        p = fmaf(p, u, -2.6866171e-2f);
        p = fmaf(p, u,  1.1283792e-1f);
        p = fmaf(p, u, -3.7612639e-1f);
        p = fmaf(p, u,  1.1283791671f);
        r = z * p;
    } else {
        r = erff(z);
    }
    return 0.5f * x * (1.0f + r);
}

// ---------------- permute + split kernels ----------------
// x[row, c*16+t] -> xh/xl[t][row][64] (bf16x2)
__global__ void permute_x_split(const float* __restrict__ x) {
    __shared__ float s[128 * 17];
    const int row = blockIdx.x;
    const float* src = x + (size_t)row * 2048;
    for (int i = threadIdx.x; i < 2048; i += TPB) {
        int c = i >> 4, t = i & 15;
        s[c * 17 + t] = src[i];
    }
    __syncthreads();
    for (int i = threadIdx.x; i < 1024; i += TPB) {
        int t = i >> 6, cp = i & 63;
        float f0 = s[(2 * cp) * 17 + t];
        float f1 = s[(2 * cp + 1) * 17 + t];
        uint32_t hh, ll;
        split2(f0, f1, hh, ll);
        size_t o = ((size_t)t * B_ROWS + row) * 64 + cp;
        g_xh[o] = hh;
        g_xl[o] = ll;
    }
}

// w1[o, c, t] -> w1h/w1l[t][o][64]
__global__ void permute_w1_split(const float* __restrict__ w) {
    int idx = blockIdx.x * TPB + threadIdx.x;       // 0 .. 512*64-1
    int o = idx >> 6, cp = idx & 63;
    const float* src = w + ((size_t)(o * 128 + 2 * cp)) * 16;
    float buf[32];
#pragma unroll
    for (int q = 0; q < 8; q++) {
        float4 v = *(const float4*)(src + q * 4);
        buf[q * 4 + 0] = v.x; buf[q * 4 + 1] = v.y;
        buf[q * 4 + 2] = v.z; buf[q * 4 + 3] = v.w;
    }
#pragma unroll
    for (int t = 0; t < TOK; t++) {
        uint32_t hh, ll;
        split2(buf[t], buf[16 + t], hh, ll);
        g_w1h[t * 32768 + idx] = hh;
        g_w1l[t * 32768 + idx] = ll;
    }
}

// w2[o, k, t] -> w2h/w2l[t][o][256]
__global__ void permute_w2_split(const float* __restrict__ w) {
    int idx = blockIdx.x * TPB + threadIdx.x;       // 0 .. 128*256-1
    int o = idx >> 8, kp = idx & 255;
    const float* src = w + ((size_t)(o * 512 + 2 * kp)) * 16;
    float buf[32];
#pragma unroll
    for (int q = 0; q < 8; q++) {
        float4 v = *(const float4*)(src + q * 4);
        buf[q * 4 + 0] = v.x; buf[q * 4 + 1] = v.y;
        buf[q * 4 + 2] = v.z; buf[q * 4 + 3] = v.w;
    }
#pragma unroll
    for (int t = 0; t < TOK; t++) {
        uint32_t hh, ll;
        split2(buf[t], buf[16 + t], hh, ll);
        g_w2h[t * 32768 + idx] = hh;
        g_w2l[t * 32768 + idx] = ll;
    }
}

// yp[t][row][o] -> y[row, o*16+t]
__global__ void permute_y_kernel(float* __restrict__ y) {
    __shared__ float s[128 * 17];
    const int row = blockIdx.x;
    for (int i = threadIdx.x; i < 2048; i += TPB) {
        int t = i >> 7, o = i & 127;
        s[o * 17 + t] = g_yp[((size_t)t * B_ROWS + row) * 128 + o];
    }
    __syncthreads();
    float* dst = y + (size_t)row * 2048;
    for (int i = threadIdx.x; i < 2048; i += TPB) {
        int o = i >> 4, t = i & 15;
        dst[i] = s[o * 17 + t];
    }
}

// ---------------- main mma.sync FFN kernel ----------------
// smem tiles: 128 rows x 128 bf16 cols, row pitch 256B, 16B-chunk xor swizzle:
//   byte_off(r, chunk) = r*256 + ((chunk ^ (r&7)) << 4)
#define SM_XH 0
#define SM_XL 32768
#define SM_WH 65536
#define SM_WL 98304
#define SM_HH 131072
#define SM_HL 163840
#define SM_TOTAL 196608

// cooperative tile load gmem->smem with swizzle; 128 rows x 16 uint4
__device__ __forceinline__ void load_tile(char* smem, int dstOff,
                                          const uint4* __restrict__ src,
                                          int pitch_u4, int tid) {
#pragma unroll
    for (int i = 0; i < 8; i++) {
        int lin = i * TPB + tid;
        int r = lin >> 4, c = lin & 15;
        uint32_t off = (uint32_t)r * 256 + (uint32_t)((c ^ (r & 7)) << 4);
        *(uint4*)(smem + dstOff + off) = src[r * pitch_u4 + c];
    }
}

__global__ void __launch_bounds__(TPB, 1) ffn_mma_kernel() {
    extern __shared__ char smem[];
    const uint32_t sb = smem_to_u32(smem);
    const int tid = threadIdx.x;
    const int lane = tid & 31;
    const int wid = tid >> 5;
    const int wm = wid >> 2;        // 0..1 (64-row half)
    const int wn = wid & 3;         // 0..3 (32-col quarter)
    const int bid = blockIdx.x;
    const int t = bid >> 7;         // same-t CTAs adjacent -> weights L2-hot
    const int m0 = (bid & 127) * 128;

    // per-thread ldmatrix address components
    const int rx = lane & 7;                       // xor swizzle key (row&7)
    const int a_row16 = ((lane >> 3) & 1) * 8 + rx;   // row within 16
    const int a_cs = lane >> 4;                        // 0/1: k-chunk select
    const int b_row16 = ((lane >> 4) & 1) * 8 + rx;
    const int b_cs = (lane >> 3) & 1;

    uint32_t aoff[4], boff[2];
#pragma unroll
    for (int i = 0; i < 4; i++)
        aoff[i] = (uint32_t)(wm * 64 + i * 16 + a_row16) * 256;
#pragma unroll
    for (int j = 0; j < 2; j++)
        boff[j] = (uint32_t)(wn * 32 + j * 16 + b_row16) * 256;

    // ---- stage X hi/lo ----
    {
        const uint4* xh = (const uint4*)(g_xh + ((size_t)t * B_ROWS + m0) * 64);
        const uint4* xl = (const uint4*)(g_xl + ((size_t)t * B_ROWS + m0) * 64);
        load_tile(smem, SM_XH, xh, 16, tid);
        load_tile(smem, SM_XL, xl, 16, tid);
    }

    const uint4* w1h = (const uint4*)(g_w1h + (size_t)t * 32768);
    const uint4* w1l = (const uint4*)(g_w1l + (size_t)t * 32768);
    const uint4* w2h = (const uint4*)(g_w2h + (size_t)t * 32768);
    const uint4* w2l = (const uint4*)(g_w2l + (size_t)t * 32768);

    float c2[4][4][4];   // persistent GEMM2 accum: [m-frag][n-frag][4]
#pragma unroll
    for (int i = 0; i < 4; i++)
#pragma unroll
        for (int n = 0; n < 4; n++)
#pragma unroll
            for (int q = 0; q < 4; q++) c2[i][n][q] = 0.0f;

    for (int j = 0; j < 4; j++) {
        // ---- W1 chunk j ----
        __syncthreads();   // Wbuf free, (j=0: X staged)
        load_tile(smem, SM_WH, w1h + (size_t)(j * 128) * 16, 16, tid);
        load_tile(smem, SM_WL, w1l + (size_t)(j * 128) * 16, 16, tid);
        __syncthreads();

        // ---- GEMM1: c1 = Xh*Wh + Xh*Wl + Xl*Wh ----
        float c1[4][4][4];
#pragma unroll
        for (int i = 0; i < 4; i++)
#pragma unroll
            for (int n = 0; n < 4; n++)
#pragma unroll
                for (int q = 0; q < 4; q++) c1[i][n][q] = 0.0f;

#pragma unroll
        for (int p = 0; p < 3; p++) {
            const uint32_t abase = sb + ((p == 2) ? SM_XL : SM_XH);
            const uint32_t bbase = sb + ((p == 1) ? SM_WL : SM_WH);
#pragma unroll
            for (int k = 0; k < 8; k++) {
                uint32_t asw = (uint32_t)(((2 * k + a_cs) ^ rx) << 4);
                uint32_t bsw = (uint32_t)(((2 * k + b_cs) ^ rx) << 4);
                uint32_t a[4][4], b[2][4];
#pragma unroll
                for (int i = 0; i < 4; i++) ldsm4(a[i], abase + aoff[i] + asw);
#pragma unroll
                for (int jb = 0; jb < 2; jb++) ldsm4(b[jb], bbase + boff[jb] + bsw);
#pragma unroll
                for (int i = 0; i < 4; i++)
#pragma unroll
                    for (int n = 0; n < 4; n++)
                        mma_bf16(c1[i][n], a[i], b[n >> 1][(n & 1) * 2],
                                 b[n >> 1][(n & 1) * 2 + 1]);
            }
        }

        // ---- GELU + split -> H tiles ----
        {
            const int g = lane >> 2, tt = lane & 3;
#pragma unroll
            for (int i = 0; i < 4; i++) {
#pragma unroll
                for (int n = 0; n < 4; n++) {
                    int col = wn * 32 + n * 8 + 2 * tt;
                    int chunk = col >> 3, cb = (col & 7) * 2;
                    int r0 = wm * 64 + i * 16 + g;
                    uint32_t off0 = (uint32_t)r0 * 256 +
                                    (uint32_t)((chunk ^ (r0 & 7)) << 4) + cb;
                    int r1 = r0 + 8;
                    uint32_t off1 = (uint32_t)r1 * 256 +
                                    (uint32_t)((chunk ^ (r1 & 7)) << 4) + cb;
                    uint32_t hh, ll;
                    split2(gelu_f(c1[i][n][0]), gelu_f(c1[i][n][1]), hh, ll);
                    *(uint32_t*)(smem + SM_HH + off0) = hh;
                    *(uint32_t*)(smem + SM_HL + off0) = ll;
                    split2(gelu_f(c1[i][n][2]), gelu_f(c1[i][n][3]), hh, ll);
                    *(uint32_t*)(smem + SM_HH + off1) = hh;
                    *(uint32_t*)(smem + SM_HL + off1) = ll;
                }
            }
        }

        // ---- W2 chunk j ----
        __syncthreads();   // H complete; GEMM1 done reading Wbuf
        load_tile(smem, SM_WH, w2h + (size_t)(j * 16), 64, tid);
        load_tile(smem, SM_WL, w2l + (size_t)(j * 16), 64, tid);
        __syncthreads();

        // ---- GEMM2: c2 += Hh*Wh + Hh*Wl + Hl*Wh ----
#pragma unroll
        for (int p = 0; p < 3; p++) {
            const uint32_t abase = sb + ((p == 2) ? SM_HL : SM_HH);
            const uint32_t bbase = sb + ((p == 1) ? SM_WL : SM_WH);
#pragma unroll
            for (int k = 0; k < 8; k++) {
                uint32_t asw = (uint32_t)(((2 * k + a_cs) ^ rx) << 4);
                uint32_t bsw = (uint32_t)(((2 * k + b_cs) ^ rx) << 4);
                uint32_t a[4][4], b[2][4];
#pragma unroll
                for (int i = 0; i < 4; i++) ldsm4(a[i], abase + aoff[i] + asw);
#pragma unroll
                for (int jb = 0; jb < 2; jb++) ldsm4(b[jb], bbase + boff[jb] + bsw);
#pragma unroll
                for (int i = 0; i < 4; i++)
#pragma unroll
                    for (int n = 0; n < 4; n++)
                        mma_bf16(c2[i][n], a[i], b[n >> 1][(n & 1) * 2],
                                 b[n >> 1][(n & 1) * 2 + 1]);
            }
        }
    }

    // ---- store C2 -> g_yp [t][row][128] ----
    {
        const int g = lane >> 2, tt = lane & 3;
        float* ybase = g_yp + ((size_t)t * B_ROWS + m0) * 128;
#pragma unroll
        for (int i = 0; i < 4; i++) {
#pragma unroll
            for (int n = 0; n < 4; n++) {
                int col = wn * 32 + n * 8 + 2 * tt;
                int r0 = wm * 64 + i * 16 + g;
                *(float2*)(ybase + (size_t)r0 * 128 + col) =
                    make_float2(c2[i][n][0], c2[i][n][1]);
                *(float2*)(ybase + (size_t)(r0 + 8) * 128 + col) =
                    make_float2(c2[i][n][2], c2[i][n][3]);
            }
        }
    }
}

// ---------------- launch ----------------
extern "C" void kernel_launch(void* const* d_in, const int* in_sizes, int n_in,
                              void* d_out, int out_size) {
    const float* x  = (const float*)d_in[0];
    const float* w1 = (const float*)d_in[1];
    const float* w2 = (const float*)d_in[2];
    float* y = (float*)d_out;
    (void)in_sizes; (void)n_in; (void)out_size;

    cudaFuncSetAttribute(ffn_mma_kernel,
                         cudaFuncAttributeMaxDynamicSharedMemorySize, SM_TOTAL);

    permute_x_split<<<B_ROWS, TPB>>>(x);
    permute_w1_split<<<(512 * 64) / TPB, TPB>>>(w1);
    permute_w2_split<<<(128 * 256) / TPB, TPB>>>(w2);
    ffn_mma_kernel<<<TOK * (B_ROWS / 128), TPB, SM_TOTAL>>>();
    permute_y_kernel<<<B_ROWS, TPB>>>(y);
}

// round 6
// speedup vs baseline: 2.2472x; 1.2566x over previous
#include <cuda_runtime.h>
#include <cuda_bf16.h>
#include <math.h>
#include <stdint.h>

#define B_ROWS 16384
#define TOK 16
#define TPB 256

// ---------------- gmem scratch (static, allocation-free) ----------------
__device__ uint32_t g_xh[(size_t)TOK * B_ROWS * 64];   // [t][row][64] bf16x2 (hi)
__device__ uint32_t g_xl[(size_t)TOK * B_ROWS * 64];   // (lo)
__device__ uint32_t g_w1h[TOK * 512 * 64];             // [t][o=512][64] bf16x2
__device__ uint32_t g_w1l[TOK * 512 * 64];
__device__ uint32_t g_w2h[TOK * 128 * 256];            // [t][o=128][256] bf16x2
__device__ uint32_t g_w2l[TOK * 128 * 256];
__device__ float    g_yp[(size_t)TOK * B_ROWS * 128];  // [t][row][o] fp32

// ---------------- helpers ----------------
__device__ __forceinline__ uint32_t smem_to_u32(const void* p) {
    uint32_t a;
    asm("{ .reg .u64 t; cvta.to.shared.u64 t, %1; cvt.u32.u64 %0, t; }"
        : "=r"(a) : "l"(p));
    return a;
}
__device__ __forceinline__ void ldsm4(uint32_t r[4], uint32_t addr) {
    asm volatile("ldmatrix.sync.aligned.m8n8.x4.shared.b16 {%0,%1,%2,%3}, [%4];"
                 : "=r"(r[0]), "=r"(r[1]), "=r"(r[2]), "=r"(r[3]) : "r"(addr));
}
__device__ __forceinline__ void mma_bf16(float c[4], const uint32_t a[4],
                                         uint32_t b0, uint32_t b1) {
    asm volatile(
        "mma.sync.aligned.m16n8k16.row.col.f32.bf16.bf16.f32 "
        "{%0,%1,%2,%3}, {%4,%5,%6,%7}, {%8,%9}, {%0,%1,%2,%3};"
        : "+f"(c[0]), "+f"(c[1]), "+f"(c[2]), "+f"(c[3])
        : "r"(a[0]), "r"(a[1]), "r"(a[2]), "r"(a[3]), "r"(b0), "r"(b1));
}

#define CP_ASYNC16(dst, src) \
    asm volatile("cp.async.cg.shared.global [%0], [%1], 16;" :: "r"(dst), "l"(src))
#define CP_COMMIT() asm volatile("cp.async.commit_group;" ::: "memory")
#define CP_WAIT(n)  asm volatile("cp.async.wait_group %0;" :: "n"(n) : "memory")

__device__ __forceinline__ void split2(float f0, float f1, uint32_t& hh, uint32_t& ll) {
    __nv_bfloat16 h0 = __float2bfloat16(f0);
    __nv_bfloat16 h1 = __float2bfloat16(f1);
    float l0 = f0 - __bfloat162float(h0);
    float l1 = f1 - __bfloat162float(h1);
    __nv_bfloat16 m0 = __float2bfloat16(l0);
    __nv_bfloat16 m1 = __float2bfloat16(l1);
    hh = (uint32_t)__bfloat16_as_ushort(h0) | ((uint32_t)__bfloat16_as_ushort(h1) << 16);
    ll = (uint32_t)__bfloat16_as_ushort(m0) | ((uint32_t)__bfloat16_as_ushort(m1) << 16);
}

// exact-erf GELU: 11-term odd Taylor on |x|<=2 (err < 2.5e-6), erff tail
__device__ __forceinline__ float gelu_f(float x) {
    float z = 0.70710678118654752f * x;
    float r;
    if (fabsf(x) <= 2.0f) {
        float u = z * z;
        float p =              1.4807192e-8f;
        p = fmaf(p, u, -1.6365349e-7f);
        p = fmaf(p, u,  1.6462114e-6f);
        p = fmaf(p, u, -1.4925650e-5f);
        p = fmaf(p, u,  1.2055332e-4f);
        p = fmaf(p, u, -8.5483270e-4f);
        p = fmaf(p, u,  5.2239776e-3f);
        p = fmaf(p, u, -2.6866171e-2f);
        p = fmaf(p, u,  1.1283792e-1f);
        p = fmaf(p, u, -3.7612639e-1f);
        p = fmaf(p, u,  1.1283791671f);
        r = z * p;
    } else {
        r = erff(z);
    }
    return 0.5f * x * (1.0f + r);
}

// ---------------- permute + split kernels ----------------
__global__ void permute_x_split(const float* __restrict__ x) {
    __shared__ float s[128 * 17];
    const int row = blockIdx.x;
    const float* src = x + (size_t)row * 2048;
    for (int i = threadIdx.x; i < 2048; i += TPB) {
        int c = i >> 4, t = i & 15;
        s[c * 17 + t] = src[i];
    }
    __syncthreads();
    for (int i = threadIdx.x; i < 1024; i += TPB) {
        int t = i >> 6, cp = i & 63;
        float f0 = s[(2 * cp) * 17 + t];
        float f1 = s[(2 * cp + 1) * 17 + t];
        uint32_t hh, ll;
        split2(f0, f1, hh, ll);
        size_t o = ((size_t)t * B_ROWS + row) * 64 + cp;
        g_xh[o] = hh;
        g_xl[o] = ll;
    }
}

__global__ void permute_w1_split(const float* __restrict__ w) {
    int idx = blockIdx.x * TPB + threadIdx.x;       // 0 .. 512*64-1
    int o = idx >> 6, cp = idx & 63;
    const float* src = w + ((size_t)(o * 128 + 2 * cp)) * 16;
    float buf[32];
#pragma unroll
    for (int q = 0; q < 8; q++) {
        float4 v = *(const float4*)(src + q * 4);
        buf[q * 4 + 0] = v.x; buf[q * 4 + 1] = v.y;
        buf[q * 4 + 2] = v.z; buf[q * 4 + 3] = v.w;
    }
#pragma unroll
    for (int t = 0; t < TOK; t++) {
        uint32_t hh, ll;
        split2(buf[t], buf[16 + t], hh, ll);
        g_w1h[t * 32768 + idx] = hh;
        g_w1l[t * 32768 + idx] = ll;
    }
}

__global__ void permute_w2_split(const float* __restrict__ w) {
    int idx = blockIdx.x * TPB + threadIdx.x;       // 0 .. 128*256-1
    int o = idx >> 8, kp = idx & 255;
    const float* src = w + ((size_t)(o * 512 + 2 * kp)) * 16;
    float buf[32];
#pragma unroll
    for (int q = 0; q < 8; q++) {
        float4 v = *(const float4*)(src + q * 4);
        buf[q * 4 + 0] = v.x; buf[q * 4 + 1] = v.y;
        buf[q * 4 + 2] = v.z; buf[q * 4 + 3] = v.w;
    }
#pragma unroll
    for (int t = 0; t < TOK; t++) {
        uint32_t hh, ll;
        split2(buf[t], buf[16 + t], hh, ll);
        g_w2h[t * 32768 + idx] = hh;
        g_w2l[t * 32768 + idx] = ll;
    }
}

__global__ void permute_y_kernel(float* __restrict__ y) {
    __shared__ float s[128 * 17];
    const int row = blockIdx.x;
    for (int i = threadIdx.x; i < 2048; i += TPB) {
        int t = i >> 7, o = i & 127;
        s[o * 17 + t] = g_yp[((size_t)t * B_ROWS + row) * 128 + o];
    }
    __syncthreads();
    float* dst = y + (size_t)row * 2048;
    for (int i = threadIdx.x; i < 2048; i += TPB) {
        int o = i >> 4, t = i & 15;
        dst[i] = s[o * 17 + t];
    }
}

// ---------------- main pipelined mma.sync FFN kernel ----------------
// smem map (bytes):
//   XH 0 (32K) | XL 32768 (32K)                       pitch 256B, 128x128 bf16
//   HH 65536 (16K) | HL 81920 (16K)                   pitch 128B, 128x64 bf16
//   W1 bufs: 98304  + b*32768 (h at +0, l at +16384)  pitch 256B, 64x128 bf16
//   W2 bufs: 163840 + b*32768 (h at +0, l at +16384)  pitch 128B, 128x64 bf16
#define SM_XH 0
#define SM_XL 32768
#define SM_HH 65536
#define SM_HL 81920
#define SM_W1 98304
#define SM_W2 163840
#define SM_TOTAL 229376

// W1 chunk: 64 rows x 16 uint4, pitch 256B, swizzled
__device__ __forceinline__ void cpa_w1(uint32_t sb, int buf,
                                       const uint4* __restrict__ h,
                                       const uint4* __restrict__ l, int tid) {
    uint32_t base = sb + SM_W1 + buf * 32768;
#pragma unroll
    for (int i = 0; i < 4; i++) {
        int lin = i * TPB + tid;
        int r = lin >> 4, c = lin & 15;
        uint32_t off = (uint32_t)r * 256 + (uint32_t)((c ^ (r & 7)) << 4);
        CP_ASYNC16(base + off, h + r * 16 + c);
        CP_ASYNC16(base + 16384 + off, l + r * 16 + c);
    }
}
// W2 chunk: 128 rows x 8 uint4, pitch 128B, swizzled; gmem row stride 64 uint4
__device__ __forceinline__ void cpa_w2(uint32_t sb, int buf,
                                       const uint4* __restrict__ h,
                                       const uint4* __restrict__ l, int tid) {
    uint32_t base = sb + SM_W2 + buf * 32768;
#pragma unroll
    for (int i = 0; i < 4; i++) {
        int lin = i * TPB + tid;
        int r = lin >> 3, c = lin & 7;
        uint32_t off = (uint32_t)r * 128 + (uint32_t)((c ^ (r & 7)) << 4);
        CP_ASYNC16(base + off, h + r * 64 + c);
        CP_ASYNC16(base + 16384 + off, l + r * 64 + c);
    }
}

__global__ void __launch_bounds__(TPB, 1) ffn_mma_kernel() {
    extern __shared__ char smem[];
    const uint32_t sb = smem_to_u32(smem);
    const int tid = threadIdx.x;
    const int lane = tid & 31;
    const int wid = tid >> 5;
    const int wm = wid >> 2;        // 0..1 (64-row half)
    const int wn = wid & 3;         // 0..3
    const int bid = blockIdx.x;
    const int t = bid >> 7;         // same-t CTAs adjacent -> weights L2-hot
    const int m0 = (bid & 127) * 128;

    const int rx = lane & 7;
    const int a_row16 = ((lane >> 3) & 1) * 8 + rx;
    const int a_cs = lane >> 4;
    const int b_row16 = ((lane >> 4) & 1) * 8 + rx;
    const int b_cs = (lane >> 3) & 1;

    uint32_t aoffX[4], aoffH[4];
#pragma unroll
    for (int i = 0; i < 4; i++) {
        aoffX[i] = (uint32_t)(wm * 64 + i * 16 + a_row16) * 256;
        aoffH[i] = (uint32_t)(wm * 64 + i * 16 + a_row16) * 128;
    }
    const uint32_t boff1 = (uint32_t)(wn * 16 + b_row16) * 256;
    uint32_t boff2[2];
#pragma unroll
    for (int jb = 0; jb < 2; jb++)
        boff2[jb] = (uint32_t)(wn * 32 + jb * 16 + b_row16) * 128;

    const uint4* w1h = (const uint4*)(g_w1h + (size_t)t * 32768);
    const uint4* w1l = (const uint4*)(g_w1l + (size_t)t * 32768);
    const uint4* w2h = (const uint4*)(g_w2h + (size_t)t * 32768);
    const uint4* w2l = (const uint4*)(g_w2l + (size_t)t * 32768);

    // ---- prologue: X hi/lo + W1(0) + W2(0) via cp.async ----
    {
        const uint4* xh = (const uint4*)(g_xh + ((size_t)t * B_ROWS + m0) * 64);
        const uint4* xl = (const uint4*)(g_xl + ((size_t)t * B_ROWS + m0) * 64);
#pragma unroll
        for (int i = 0; i < 8; i++) {
            int lin = i * TPB + tid;
            int r = lin >> 4, c = lin & 15;
            uint32_t off = (uint32_t)r * 256 + (uint32_t)((c ^ (r & 7)) << 4);
            CP_ASYNC16(sb + SM_XH + off, xh + r * 16 + c);
            CP_ASYNC16(sb + SM_XL + off, xl + r * 16 + c);
        }
        cpa_w1(sb, 0, w1h, w1l, tid);
        cpa_w2(sb, 0, w2h, w2l, tid);
        CP_COMMIT();
        CP_WAIT(0);
        __syncthreads();
    }

    float c2[4][4][4];
#pragma unroll
    for (int i = 0; i < 4; i++)
#pragma unroll
        for (int n = 0; n < 4; n++)
#pragma unroll
            for (int q = 0; q < 4; q++) c2[i][n][q] = 0.0f;

    const int g = lane >> 2, tt = lane & 3;

    for (int j = 0; j < 8; j++) {
        if (j > 0) {
            CP_WAIT(1);          // W1(j) arrived (W2(j) may still be in flight)
            __syncthreads();
        }
        const uint32_t w1b = sb + SM_W1 + (j & 1) * 32768;
        const uint32_t w2b = sb + SM_W2 + (j & 1) * 32768;

        if (j < 7) {             // prefetch W1(j+1) under GEMM1
            cpa_w1(sb, (j + 1) & 1, w1h + (size_t)((j + 1) * 64) * 16,
                   w1l + (size_t)((j + 1) * 64) * 16, tid);
            CP_COMMIT();
        }

        // ---- GEMM1 (fused 3-pass): c1 = Xh*Wh + Xh*Wl + Xl*Wh ----
        float c1[4][2][4];
#pragma unroll
        for (int i = 0; i < 4; i++)
#pragma unroll
            for (int n = 0; n < 2; n++)
#pragma unroll
                for (int q = 0; q < 4; q++) c1[i][n][q] = 0.0f;

#pragma unroll
        for (int k = 0; k < 8; k++) {
            uint32_t asw = (uint32_t)(((2 * k + a_cs) ^ rx) << 4);
            uint32_t bsw = (uint32_t)(((2 * k + b_cs) ^ rx) << 4);
            uint32_t ah[4][4], al[4][4], bh[4], bl[4];
#pragma unroll
            for (int i = 0; i < 4; i++) {
                ldsm4(ah[i], sb + SM_XH + aoffX[i] + asw);
                ldsm4(al[i], sb + SM_XL + aoffX[i] + asw);
            }
            ldsm4(bh, w1b + boff1 + bsw);
            ldsm4(bl, w1b + 16384 + boff1 + bsw);
#pragma unroll
            for (int i = 0; i < 4; i++)
#pragma unroll
                for (int n = 0; n < 2; n++) {
                    mma_bf16(c1[i][n], ah[i], bh[n * 2], bh[n * 2 + 1]);
                    mma_bf16(c1[i][n], ah[i], bl[n * 2], bl[n * 2 + 1]);
                    mma_bf16(c1[i][n], al[i], bh[n * 2], bh[n * 2 + 1]);
                }
        }

        // ---- GELU + split -> H tiles (pitch 128B) ----
#pragma unroll
        for (int i = 0; i < 4; i++) {
#pragma unroll
            for (int n = 0; n < 2; n++) {
                int col = wn * 16 + n * 8 + 2 * tt;
                int chunk = col >> 3, cb = (col & 7) * 2;
                int r0 = wm * 64 + i * 16 + g;
                int r1 = r0 + 8;
                uint32_t off0 = (uint32_t)r0 * 128 +
                                (uint32_t)((chunk ^ (r0 & 7)) << 4) + cb;
                uint32_t off1 = (uint32_t)r1 * 128 +
                                (uint32_t)((chunk ^ (r1 & 7)) << 4) + cb;
                uint32_t hh, ll;
                split2(gelu_f(c1[i][n][0]), gelu_f(c1[i][n][1]), hh, ll);
                *(uint32_t*)(smem + SM_HH + off0) = hh;
                *(uint32_t*)(smem + SM_HL + off0) = ll;
                split2(gelu_f(c1[i][n][2]), gelu_f(c1[i][n][3]), hh, ll);
                *(uint32_t*)(smem + SM_HH + off1) = hh;
                *(uint32_t*)(smem + SM_HL + off1) = ll;
            }
        }

        if (j < 7) {             // prefetch W2(j+1) under GEMM2
            cpa_w2(sb, (j + 1) & 1, w2h + (size_t)(j + 1) * 8,
                   w2l + (size_t)(j + 1) * 8, tid);
            CP_COMMIT();
            CP_WAIT(2);          // W2(j) arrived
        } else {
            CP_WAIT(0);
        }
        __syncthreads();         // H visible; W2(j) visible

        // ---- GEMM2 (fused 3-pass): c2 += Hh*Wh + Hh*Wl + Hl*Wh ----
#pragma unroll
        for (int k = 0; k < 4; k++) {
            uint32_t asw = (uint32_t)(((2 * k + a_cs) ^ rx) << 4);
            uint32_t bsw = (uint32_t)(((2 * k + b_cs) ^ rx) << 4);
            uint32_t ah[4][4], al[4][4], bh2[2][4], bl2[2][4];
#pragma unroll
            for (int i = 0; i < 4; i++) {
                ldsm4(ah[i], sb + SM_HH + aoffH[i] + asw);
                ldsm4(al[i], sb + SM_HL + aoffH[i] + asw);
            }
#pragma unroll
            for (int jb = 0; jb < 2; jb++) {
                ldsm4(bh2[jb], w2b + boff2[jb] + bsw);
                ldsm4(bl2[jb], w2b + 16384 + boff2[jb] + bsw);
            }
#pragma unroll
            for (int i = 0; i < 4; i++)
#pragma unroll
                for (int n = 0; n < 4; n++) {
                    int jb = n >> 1, sel = (n & 1) * 2;
                    mma_bf16(c2[i][n], ah[i], bh2[jb][sel], bh2[jb][sel + 1]);
                    mma_bf16(c2[i][n], ah[i], bl2[jb][sel], bl2[jb][sel + 1]);
                    mma_bf16(c2[i][n], al[i], bh2[jb][sel], bh2[jb][sel + 1]);
                }
        }
    }

    // ---- store C2 -> g_yp [t][row][128] ----
    {
        float* ybase = g_yp + ((size_t)t * B_ROWS + m0) * 128;
#pragma unroll
        for (int i = 0; i < 4; i++) {
#pragma unroll
            for (int n = 0; n < 4; n++) {
                int col = wn * 32 + n * 8 + 2 * tt;
                int r0 = wm * 64 + i * 16 + g;
                *(float2*)(ybase + (size_t)r0 * 128 + col) =
                    make_float2(c2[i][n][0], c2[i][n][1]);
                *(float2*)(ybase + (size_t)(r0 + 8) * 128 + col) =
                    make_float2(c2[i][n][2], c2[i][n][3]);
            }
        }
    }
}

// ---------------- launch ----------------
extern "C" void kernel_launch(void* const* d_in, const int* in_sizes, int n_in,
                              void* d_out, int out_size) {
    const float* x  = (const float*)d_in[0];
    const float* w1 = (const float*)d_in[1];
    const float* w2 = (const float*)d_in[2];
    float* y = (float*)d_out;
    (void)in_sizes; (void)n_in; (void)out_size;

    cudaFuncSetAttribute(ffn_mma_kernel,
                         cudaFuncAttributeMaxDynamicSharedMemorySize, SM_TOTAL);

    permute_x_split<<<B_ROWS, TPB>>>(x);
    permute_w1_split<<<(512 * 64) / TPB, TPB>>>(w1);
    permute_w2_split<<<(128 * 256) / TPB, TPB>>>(w2);
    ffn_mma_kernel<<<TOK * (B_ROWS / 128), TPB, SM_TOTAL>>>();
    permute_y_kernel<<<B_ROWS, TPB>>>(y);
}

// round 7
// speedup vs baseline: 2.2618x; 1.0065x over previous
#include <cuda_runtime.h>
#include <cuda_bf16.h>
#include <math.h>
#include <stdint.h>

#define B_ROWS 16384
#define TOK 16
#define TPB 256

// ---------------- gmem scratch (static, allocation-free) ----------------
__device__ uint32_t g_xh[(size_t)TOK * B_ROWS * 64];   // [t][row][64] bf16x2 (hi)
__device__ uint32_t g_xl[(size_t)TOK * B_ROWS * 64];   // (lo)
__device__ uint32_t g_w1h[TOK * 512 * 64];             // [t][o=512][64] bf16x2
__device__ uint32_t g_w1l[TOK * 512 * 64];
__device__ uint32_t g_w2h[TOK * 128 * 256];            // [t][o=128][256] bf16x2
__device__ uint32_t g_w2l[TOK * 128 * 256];
__device__ float    g_yp[(size_t)TOK * B_ROWS * 128];  // [t][row][o] fp32

// ---------------- helpers ----------------
__device__ __forceinline__ uint32_t smem_to_u32(const void* p) {
    uint32_t a;
    asm("{ .reg .u64 t; cvta.to.shared.u64 t, %1; cvt.u32.u64 %0, t; }"
        : "=r"(a) : "l"(p));
    return a;
}
__device__ __forceinline__ void ldsm4(uint32_t r[4], uint32_t addr) {
    asm volatile("ldmatrix.sync.aligned.m8n8.x4.shared.b16 {%0,%1,%2,%3}, [%4];"
                 : "=r"(r[0]), "=r"(r[1]), "=r"(r[2]), "=r"(r[3]) : "r"(addr));
}
__device__ __forceinline__ void mma_bf16(float c[4], const uint32_t a[4],
                                         uint32_t b0, uint32_t b1) {
    asm volatile(
        "mma.sync.aligned.m16n8k16.row.col.f32.bf16.bf16.f32 "
        "{%0,%1,%2,%3}, {%4,%5,%6,%7}, {%8,%9}, {%0,%1,%2,%3};"
        : "+f"(c[0]), "+f"(c[1]), "+f"(c[2]), "+f"(c[3])
        : "r"(a[0]), "r"(a[1]), "r"(a[2]), "r"(a[3]), "r"(b0), "r"(b1));
}

#define CP_ASYNC16(dst, src) \
    asm volatile("cp.async.cg.shared.global [%0], [%1], 16;" :: "r"(dst), "l"(src))
#define CP_COMMIT() asm volatile("cp.async.commit_group;" ::: "memory")
#define CP_WAIT(n)  asm volatile("cp.async.wait_group %0;" :: "n"(n) : "memory")

__device__ __forceinline__ void split2(float f0, float f1, uint32_t& hh, uint32_t& ll) {
    __nv_bfloat16 h0 = __float2bfloat16(f0);
    __nv_bfloat16 h1 = __float2bfloat16(f1);
    float l0 = f0 - __bfloat162float(h0);
    float l1 = f1 - __bfloat162float(h1);
    __nv_bfloat16 m0 = __float2bfloat16(l0);
    __nv_bfloat16 m1 = __float2bfloat16(l1);
    hh = (uint32_t)__bfloat16_as_ushort(h0) | ((uint32_t)__bfloat16_as_ushort(h1) << 16);
    ll = (uint32_t)__bfloat16_as_ushort(m0) | ((uint32_t)__bfloat16_as_ushort(m1) << 16);
}

// exact-erf GELU: 11-term odd Taylor on |x|<=2 (err < 2.5e-6), erff tail
__device__ __forceinline__ float gelu_f(float x) {
    float z = 0.70710678118654752f * x;
    float r;
    if (fabsf(x) <= 2.0f) {
        float u = z * z;
        float p =              1.4807192e-8f;
        p = fmaf(p, u, -1.6365349e-7f);
        p = fmaf(p, u,  1.6462114e-6f);
        p = fmaf(p, u, -1.4925650e-5f);
        p = fmaf(p, u,  1.2055332e-4f);
        p = fmaf(p, u, -8.5483270e-4f);
        p = fmaf(p, u,  5.2239776e-3f);
        p = fmaf(p, u, -2.6866171e-2f);
        p = fmaf(p, u,  1.1283792e-1f);
        p = fmaf(p, u, -3.7612639e-1f);
        p = fmaf(p, u,  1.1283791671f);
        r = z * p;
    } else {
        r = erff(z);
    }
    return 0.5f * x * (1.0f + r);
}

// ---------------- permute + split kernels ----------------
__global__ void permute_x_split(const float* __restrict__ x) {
    __shared__ float s[128 * 17];
    const int row = blockIdx.x;
    const float* src = x + (size_t)row * 2048;
    for (int i = threadIdx.x; i < 2048; i += TPB) {
        int c = i >> 4, t = i & 15;
        s[c * 17 + t] = src[i];
    }
    __syncthreads();
    for (int i = threadIdx.x; i < 1024; i += TPB) {
        int t = i >> 6, cp = i & 63;
        float f0 = s[(2 * cp) * 17 + t];
        float f1 = s[(2 * cp + 1) * 17 + t];
        uint32_t hh, ll;
        split2(f0, f1, hh, ll);
        size_t o = ((size_t)t * B_ROWS + row) * 64 + cp;
        g_xh[o] = hh;
        g_xl[o] = ll;
    }
}

__global__ void permute_w1_split(const float* __restrict__ w) {
    int idx = blockIdx.x * TPB + threadIdx.x;       // 0 .. 512*64-1
    int o = idx >> 6, cp = idx & 63;
    const float* src = w + ((size_t)(o * 128 + 2 * cp)) * 16;
    float buf[32];
#pragma unroll
    for (int q = 0; q < 8; q++) {
        float4 v = *(const float4*)(src + q * 4);
        buf[q * 4 + 0] = v.x; buf[q * 4 + 1] = v.y;
        buf[q * 4 + 2] = v.z; buf[q * 4 + 3] = v.w;
    }
#pragma unroll
    for (int t = 0; t < TOK; t++) {
        uint32_t hh, ll;
        split2(buf[t], buf[16 + t], hh, ll);
        g_w1h[t * 32768 + idx] = hh;
        g_w1l[t * 32768 + idx] = ll;
    }
}

__global__ void permute_w2_split(const float* __restrict__ w) {
    int idx = blockIdx.x * TPB + threadIdx.x;       // 0 .. 128*256-1
    int o = idx >> 8, kp = idx & 255;
    const float* src = w + ((size_t)(o * 512 + 2 * kp)) * 16;
    float buf[32];
#pragma unroll
    for (int q = 0; q < 8; q++) {
        float4 v = *(const float4*)(src + q * 4);
        buf[q * 4 + 0] = v.x; buf[q * 4 + 1] = v.y;
        buf[q * 4 + 2] = v.z; buf[q * 4 + 3] = v.w;
    }
#pragma unroll
    for (int t = 0; t < TOK; t++) {
        uint32_t hh, ll;
        split2(buf[t], buf[16 + t], hh, ll);
        g_w2h[t * 32768 + idx] = hh;
        g_w2l[t * 32768 + idx] = ll;
    }
}

__global__ void permute_y_kernel(float* __restrict__ y) {
    __shared__ float s[128 * 17];
    const int row = blockIdx.x;
    for (int i = threadIdx.x; i < 2048; i += TPB) {
        int t = i >> 7, o = i & 127;
        s[o * 17 + t] = g_yp[((size_t)t * B_ROWS + row) * 128 + o];
    }
    __syncthreads();
    float* dst = y + (size_t)row * 2048;
    for (int i = threadIdx.x; i < 2048; i += TPB) {
        int o = i >> 4, t = i & 15;
        dst[i] = s[o * 17 + t];
    }
}

// ---------------- main warp-row-owned mma.sync FFN kernel ----------------
// Each warp owns 16 rows and the FULL N of each chunk: H stays in registers
// (GEMM1 C-frag layout == GEMM2 A-frag layout), zero intra-chunk barriers.
// smem map (bytes):
//   XH 0 (32K) | XL 32768 (32K)                      pitch 256B, 128x128 bf16
//   W1 bufs: 65536  + b*32768 (h +0, l +16384)       pitch 256B, 64x128 bf16
//   W2 bufs: 131072 + b*32768 (h +0, l +16384)       pitch 128B, 128x64 bf16
#define SM_XH 0
#define SM_XL 32768
#define SM_W1 65536
#define SM_W2 131072
#define SM_TOTAL 196608

// W1 chunk: 64 rows x 16 uint4, pitch 256B, swizzled
__device__ __forceinline__ void cpa_w1(uint32_t sb, int buf,
                                       const uint4* __restrict__ h,
                                       const uint4* __restrict__ l, int tid) {
    uint32_t base = sb + SM_W1 + buf * 32768;
#pragma unroll
    for (int i = 0; i < 4; i++) {
        int lin = i * TPB + tid;
        int r = lin >> 4, c = lin & 15;
        uint32_t off = (uint32_t)r * 256 + (uint32_t)((c ^ (r & 7)) << 4);
        CP_ASYNC16(base + off, h + r * 16 + c);
        CP_ASYNC16(base + 16384 + off, l + r * 16 + c);
    }
}
// W2 chunk: 128 rows x 8 uint4, pitch 128B, swizzled; gmem row stride 64 uint4
__device__ __forceinline__ void cpa_w2(uint32_t sb, int buf,
                                       const uint4* __restrict__ h,
                                       const uint4* __restrict__ l, int tid) {
    uint32_t base = sb + SM_W2 + buf * 32768;
#pragma unroll
    for (int i = 0; i < 4; i++) {
        int lin = i * TPB + tid;
        int r = lin >> 3, c = lin & 7;
        uint32_t off = (uint32_t)r * 128 + (uint32_t)((c ^ (r & 7)) << 4);
        CP_ASYNC16(base + off, h + r * 64 + c);
        CP_ASYNC16(base + 16384 + off, l + r * 64 + c);
    }
}

__global__ void __launch_bounds__(TPB, 1) ffn_mma_kernel() {
    extern __shared__ char smem[];
    const uint32_t sb = smem_to_u32(smem);
    const int tid = threadIdx.x;
    const int lane = tid & 31;
    const int wid = tid >> 5;       // warp owns rows wid*16 .. wid*16+15
    const int bid = blockIdx.x;
    const int t = bid >> 7;         // same-t CTAs adjacent -> weights L2-hot
    const int m0 = (bid & 127) * 128;

    const int rx = lane & 7;
    const int a_row16 = ((lane >> 3) & 1) * 8 + rx;
    const int a_cs = lane >> 4;
    const int b_row16 = ((lane >> 4) & 1) * 8 + rx;
    const int b_cs = (lane >> 3) & 1;

    const uint32_t aoffX = (uint32_t)(wid * 16 + a_row16) * 256;

    const uint4* w1h = (const uint4*)(g_w1h + (size_t)t * 32768);
    const uint4* w1l = (const uint4*)(g_w1l + (size_t)t * 32768);
    const uint4* w2h = (const uint4*)(g_w2h + (size_t)t * 32768);
    const uint4* w2l = (const uint4*)(g_w2l + (size_t)t * 32768);

    // ---- prologue: X hi/lo + W1(0) + W2(0) via cp.async ----
    {
        const uint4* xh = (const uint4*)(g_xh + ((size_t)t * B_ROWS + m0) * 64);
        const uint4* xl = (const uint4*)(g_xl + ((size_t)t * B_ROWS + m0) * 64);
#pragma unroll
        for (int i = 0; i < 8; i++) {
            int lin = i * TPB + tid;
            int r = lin >> 4, c = lin & 15;
            uint32_t off = (uint32_t)r * 256 + (uint32_t)((c ^ (r & 7)) << 4);
            CP_ASYNC16(sb + SM_XH + off, xh + r * 16 + c);
            CP_ASYNC16(sb + SM_XL + off, xl + r * 16 + c);
        }
        cpa_w1(sb, 0, w1h, w1l, tid);
        cpa_w2(sb, 0, w2h, w2l, tid);
        CP_COMMIT();
        CP_WAIT(0);
        __syncthreads();
    }

    // persistent GEMM2 accumulators: 16 n8-frags over 128 out cols
    float c2[16][4];
#pragma unroll
    for (int n = 0; n < 16; n++)
#pragma unroll
        for (int q = 0; q < 4; q++) c2[n][q] = 0.0f;

    for (int j = 0; j < 8; j++) {
        const uint32_t w1b = sb + SM_W1 + (j & 1) * 32768;
        const uint32_t w2b = sb + SM_W2 + (j & 1) * 32768;

        // prefetch next chunk's weights into the other buffer
        if (j < 7) {
            cpa_w1(sb, (j + 1) & 1, w1h + (size_t)((j + 1) * 64) * 16,
                   w1l + (size_t)((j + 1) * 64) * 16, tid);
            cpa_w2(sb, (j + 1) & 1, w2h + (size_t)(j + 1) * 8,
                   w2l + (size_t)(j + 1) * 8, tid);
            CP_COMMIT();
        }

        // ---- GEMM1 (fused 3-pass): c1 = Xh*W1h + Xh*W1l + Xl*W1h ----
        // warp tile: 16 rows x 64 chunk-cols -> 8 n8-frags
        float c1[8][4];
#pragma unroll
        for (int n = 0; n < 8; n++)
#pragma unroll
            for (int q = 0; q < 4; q++) c1[n][q] = 0.0f;

#pragma unroll
        for (int k = 0; k < 8; k++) {
            uint32_t asw = (uint32_t)(((2 * k + a_cs) ^ rx) << 4);
            uint32_t bsw = (uint32_t)(((2 * k + b_cs) ^ rx) << 4);
            uint32_t ah[4], al[4];
            ldsm4(ah, sb + SM_XH + aoffX + asw);
            ldsm4(al, sb + SM_XL + aoffX + asw);
#pragma unroll
            for (int grp = 0; grp < 4; grp++) {
                uint32_t bh[4], bl[4];
                uint32_t boff = (uint32_t)(grp * 16 + b_row16) * 256;
                ldsm4(bh, w1b + boff + bsw);
                ldsm4(bl, w1b + 16384 + boff + bsw);
                mma_bf16(c1[grp * 2], ah, bh[0], bh[1]);
                mma_bf16(c1[grp * 2], ah, bl[0], bl[1]);
                mma_bf16(c1[grp * 2], al, bh[0], bh[1]);
                mma_bf16(c1[grp * 2 + 1], ah, bh[2], bh[3]);
                mma_bf16(c1[grp * 2 + 1], ah, bl[2], bl[3]);
                mma_bf16(c1[grp * 2 + 1], al, bh[2], bh[3]);
            }
        }

        // ---- GELU + split in registers: C-frags -> GEMM2 A-frags ----
        // H[g][16f+2tt..] == c1[2f]{0,1}, c1[2f+1]{0,1}; rows g+8 in {2,3}
        uint32_t a2h[4][4], a2l[4][4];
#pragma unroll
        for (int f = 0; f < 4; f++) {
            split2(gelu_f(c1[2 * f][0]), gelu_f(c1[2 * f][1]),
                   a2h[f][0], a2l[f][0]);
            split2(gelu_f(c1[2 * f][2]), gelu_f(c1[2 * f][3]),
                   a2h[f][1], a2l[f][1]);
            split2(gelu_f(c1[2 * f + 1][0]), gelu_f(c1[2 * f + 1][1]),
                   a2h[f][2], a2l[f][2]);
            split2(gelu_f(c1[2 * f + 1][2]), gelu_f(c1[2 * f + 1][3]),
                   a2h[f][3], a2l[f][3]);
        }

        // ---- GEMM2 (fused 3-pass): c2 += Hh*W2h + Hh*W2l + Hl*W2h ----
#pragma unroll
        for (int f = 0; f < 4; f++) {
            uint32_t bsw = (uint32_t)(((2 * f + b_cs) ^ rx) << 4);
#pragma unroll
            for (int grp = 0; grp < 8; grp++) {
                uint32_t bh[4], bl[4];
                uint32_t boff = (uint32_t)(grp * 16 + b_row16) * 128;
                ldsm4(bh, w2b + boff + bsw);
                ldsm4(bl, w2b + 16384 + boff + bsw);
                mma_bf16(c2[grp * 2], a2h[f], bh[0], bh[1]);
                mma_bf16(c2[grp * 2], a2h[f], bl[0], bl[1]);
                mma_bf16(c2[grp * 2], a2l[f], bh[0], bh[1]);
                mma_bf16(c2[grp * 2 + 1], a2h[f], bh[2], bh[3]);
                mma_bf16(c2[grp * 2 + 1], a2h[f], bl[2], bl[3]);
                mma_bf16(c2[grp * 2 + 1], a2l[f], bh[2], bh[3]);
            }
        }

        // rotate weight buffers (single barrier per chunk)
        if (j < 7) {
            CP_WAIT(0);
            __syncthreads();
        }
    }

    // ---- store C2 -> g_yp [t][row][128] ----
    {
        const int g = lane >> 2, tt = lane & 3;
        float* ybase = g_yp + ((size_t)t * B_ROWS + m0 + wid * 16) * 128;
#pragma unroll
        for (int n = 0; n < 16; n++) {
            int col = n * 8 + 2 * tt;
            *(float2*)(ybase + (size_t)g * 128 + col) =
                make_float2(c2[n][0], c2[n][1]);
            *(float2*)(ybase + (size_t)(g + 8) * 128 + col) =
                make_float2(c2[n][2], c2[n][3]);
        }
    }
}

// ---------------- launch ----------------
extern "C" void kernel_launch(void* const* d_in, const int* in_sizes, int n_in,
                              void* d_out, int out_size) {
    const float* x  = (const float*)d_in[0];
    const float* w1 = (const float*)d_in[1];
    const float* w2 = (const float*)d_in[2];
    float* y = (float*)d_out;
    (void)in_sizes; (void)n_in; (void)out_size;

    cudaFuncSetAttribute(ffn_mma_kernel,
                         cudaFuncAttributeMaxDynamicSharedMemorySize, SM_TOTAL);

    permute_x_split<<<B_ROWS, TPB>>>(x);
    permute_w1_split<<<(512 * 64) / TPB, TPB>>>(w1);
    permute_w2_split<<<(128 * 256) / TPB, TPB>>>(w2);
    ffn_mma_kernel<<<TOK * (B_ROWS / 128), TPB, SM_TOTAL>>>();
    permute_y_kernel<<<B_ROWS, TPB>>>(y);
}

// round 8
// speedup vs baseline: 2.5395x; 1.1228x over previous
#include <cuda_runtime.h>
#include <cuda_bf16.h>
#include <math.h>
#include <stdint.h>

#define B_ROWS 16384
#define TOK 16
#define TPB 256

// ---------------- gmem scratch (static, allocation-free) ----------------
__device__ uint32_t g_xh[(size_t)TOK * B_ROWS * 64];   // [t][row][64] bf16x2 (hi)
__device__ uint32_t g_xl[(size_t)TOK * B_ROWS * 64];   // (lo)
__device__ uint32_t g_w1h[TOK * 512 * 64];             // [t][o=512][64] bf16x2
__device__ uint32_t g_w1l[TOK * 512 * 64];
__device__ uint32_t g_w2h[TOK * 128 * 256];            // [t][o=128][256] bf16x2
__device__ uint32_t g_w2l[TOK * 128 * 256];
__device__ float    g_yp[(size_t)TOK * B_ROWS * 128];  // [t][row][o] fp32

// ---------------- helpers ----------------
__device__ __forceinline__ uint32_t smem_to_u32(const void* p) {
    uint32_t a;
    asm("{ .reg .u64 t; cvta.to.shared.u64 t, %1; cvt.u32.u64 %0, t; }"
        : "=r"(a) : "l"(p));
    return a;
}
__device__ __forceinline__ void ldsm4(uint32_t r[4], uint32_t addr) {
    asm volatile("ldmatrix.sync.aligned.m8n8.x4.shared.b16 {%0,%1,%2,%3}, [%4];"
                 : "=r"(r[0]), "=r"(r[1]), "=r"(r[2]), "=r"(r[3]) : "r"(addr));
}
__device__ __forceinline__ void mma_bf16(float c[4], const uint32_t a[4],
                                         uint32_t b0, uint32_t b1) {
    asm volatile(
        "mma.sync.aligned.m16n8k16.row.col.f32.bf16.bf16.f32 "
        "{%0,%1,%2,%3}, {%4,%5,%6,%7}, {%8,%9}, {%0,%1,%2,%3};"
        : "+f"(c[0]), "+f"(c[1]), "+f"(c[2]), "+f"(c[3])
        : "r"(a[0]), "r"(a[1]), "r"(a[2]), "r"(a[3]), "r"(b0), "r"(b1));
}

#define CP_ASYNC16(dst, src) \
    asm volatile("cp.async.cg.shared.global [%0], [%1], 16;" :: "r"(dst), "l"(src))
#define CP_COMMIT() asm volatile("cp.async.commit_group;" ::: "memory")
#define CP_WAIT(n)  asm volatile("cp.async.wait_group %0;" :: "n"(n) : "memory")

__device__ __forceinline__ void split2(float f0, float f1, uint32_t& hh, uint32_t& ll) {
    __nv_bfloat16 h0 = __float2bfloat16(f0);
    __nv_bfloat16 h1 = __float2bfloat16(f1);
    float l0 = f0 - __bfloat162float(h0);
    float l1 = f1 - __bfloat162float(h1);
    __nv_bfloat16 m0 = __float2bfloat16(l0);
    __nv_bfloat16 m1 = __float2bfloat16(l1);
    hh = (uint32_t)__bfloat16_as_ushort(h0) | ((uint32_t)__bfloat16_as_ushort(h1) << 16);
    ll = (uint32_t)__bfloat16_as_ushort(m0) | ((uint32_t)__bfloat16_as_ushort(m1) << 16);
}

// exact-erf GELU: 11-term odd Taylor on |x|<=2 (err < 2.5e-6), erff tail
__device__ __forceinline__ float gelu_f(float x) {
    float z = 0.70710678118654752f * x;
    float r;
    if (fabsf(x) <= 2.0f) {
        float u = z * z;
        float p =              1.4807192e-8f;
        p = fmaf(p, u, -1.6365349e-7f);
        p = fmaf(p, u,  1.6462114e-6f);
        p = fmaf(p, u, -1.4925650e-5f);
        p = fmaf(p, u,  1.2055332e-4f);
        p = fmaf(p, u, -8.5483270e-4f);
        p = fmaf(p, u,  5.2239776e-3f);
        p = fmaf(p, u, -2.6866171e-2f);
        p = fmaf(p, u,  1.1283792e-1f);
        p = fmaf(p, u, -3.7612639e-1f);
        p = fmaf(p, u,  1.1283791671f);
        r = z * p;
    } else {
        r = erff(z);
    }
    return 0.5f * x * (1.0f + r);
}

// ---------------- permute + split kernels ----------------
__global__ void permute_x_split(const float* __restrict__ x) {
    __shared__ float s[128 * 17];
    const int row = blockIdx.x;
    const float* src = x + (size_t)row * 2048;
    for (int i = threadIdx.x; i < 2048; i += TPB) {
        int c = i >> 4, t = i & 15;
        s[c * 17 + t] = src[i];
    }
    __syncthreads();
    for (int i = threadIdx.x; i < 1024; i += TPB) {
        int t = i >> 6, cp = i & 63;
        float f0 = s[(2 * cp) * 17 + t];
        float f1 = s[(2 * cp + 1) * 17 + t];
        uint32_t hh, ll;
        split2(f0, f1, hh, ll);
        size_t o = ((size_t)t * B_ROWS + row) * 64 + cp;
        g_xh[o] = hh;
        g_xl[o] = ll;
    }
}

__global__ void permute_w1_split(const float* __restrict__ w) {
    int idx = blockIdx.x * TPB + threadIdx.x;       // 0 .. 512*64-1
    int o = idx >> 6, cp = idx & 63;
    const float* src = w + ((size_t)(o * 128 + 2 * cp)) * 16;
    float buf[32];
#pragma unroll
    for (int q = 0; q < 8; q++) {
        float4 v = *(const float4*)(src + q * 4);
        buf[q * 4 + 0] = v.x; buf[q * 4 + 1] = v.y;
        buf[q * 4 + 2] = v.z; buf[q * 4 + 3] = v.w;
    }
#pragma unroll
    for (int t = 0; t < TOK; t++) {
        uint32_t hh, ll;
        split2(buf[t], buf[16 + t], hh, ll);
        g_w1h[t * 32768 + idx] = hh;
        g_w1l[t * 32768 + idx] = ll;
    }
}

__global__ void permute_w2_split(const float* __restrict__ w) {
    int idx = blockIdx.x * TPB + threadIdx.x;       // 0 .. 128*256-1
    int o = idx >> 8, kp = idx & 255;
    const float* src = w + ((size_t)(o * 512 + 2 * kp)) * 16;
    float buf[32];
#pragma unroll
    for (int q = 0; q < 8; q++) {
        float4 v = *(const float4*)(src + q * 4);
        buf[q * 4 + 0] = v.x; buf[q * 4 + 1] = v.y;
        buf[q * 4 + 2] = v.z; buf[q * 4 + 3] = v.w;
    }
#pragma unroll
    for (int t = 0; t < TOK; t++) {
        uint32_t hh, ll;
        split2(buf[t], buf[16 + t], hh, ll);
        g_w2h[t * 32768 + idx] = hh;
        g_w2l[t * 32768 + idx] = ll;
    }
}

__global__ void permute_y_kernel(float* __restrict__ y) {
    __shared__ float s[128 * 17];
    const int row = blockIdx.x;
    for (int i = threadIdx.x; i < 2048; i += TPB) {
        int t = i >> 7, o = i & 127;
        s[o * 17 + t] = g_yp[((size_t)t * B_ROWS + row) * 128 + o];
    }
    __syncthreads();
    float* dst = y + (size_t)row * 2048;
    for (int i = threadIdx.x; i < 2048; i += TPB) {
        int o = i >> 4, t = i & 15;
        dst[i] = s[o * 17 + t];
    }
}

// ---------------- main 2-CTA/SM mma.sync FFN kernel ----------------
// M=64 rows/CTA, chunk=32 (16 chunks). Warp grid 4 rowg x 2 colg.
// smem (104KB/CTA, 2 CTAs resident):
//   XH 0 (16K, 64r x 256B) | XL 16384
//   W1 bufs: 32768 + b*16384  (h +0 8K: 32r x 256B, l +8192)
//   W2 bufs: 65536 + b*16384  (128r x 128B, packed: h chunks0-3 | l chunks4-7)
//   H:       98304            (64r  x 128B, packed: h chunks0-3 | l chunks4-7)
#define SM_XH 0
#define SM_XL 16384
#define SM_W1 32768
#define SM_W2 65536
#define SM_H  98304
#define SM_TOTAL 106496

// W1 chunk j: 32 rows x 16 uint4 (pitch 256B, swizzled), h+l
__device__ __forceinline__ void cpa_w1(uint32_t sb, int buf,
                                       const uint4* __restrict__ h,
                                       const uint4* __restrict__ l, int tid) {
    uint32_t base = sb + SM_W1 + buf * 16384;
#pragma unroll
    for (int i = 0; i < 2; i++) {
        int lin = i * TPB + tid;          // 0..511
        int r = lin >> 4, c = lin & 15;
        uint32_t off = (uint32_t)r * 256 + (uint32_t)((c ^ (r & 7)) << 4);
        CP_ASYNC16(base + off, h + r * 16 + c);
        CP_ASYNC16(base + 8192 + off, l + r * 16 + c);
    }
}
// W2 chunk j: 128 rows x 4 uint4 each of h and l, packed into 128B rows.
// gmem rows are 64 uint4 (full K); chunk j -> uint4 cols j*4..j*4+3.
__device__ __forceinline__ void cpa_w2(uint32_t sb, int buf,
                                       const uint4* __restrict__ h,
                                       const uint4* __restrict__ l, int tid) {
    uint32_t base = sb + SM_W2 + buf * 16384;
#pragma unroll
    for (int i = 0; i < 2; i++) {
        int lin = i * TPB + tid;          // 0..511
        int r = lin >> 2, c = lin & 3;
        uint32_t offh = (uint32_t)r * 128 + (uint32_t)((c ^ (r & 7)) << 4);
        uint32_t offl = (uint32_t)r * 128 + (uint32_t)(((c + 4) ^ (r & 7)) << 4);
        CP_ASYNC16(base + offh, h + r * 64 + c);
        CP_ASYNC16(base + offl, l + r * 64 + c);
    }
}

__global__ void __launch_bounds__(TPB, 2) ffn_mma_kernel() {
    extern __shared__ char smem[];
    const uint32_t sb = smem_to_u32(smem);
    const int tid = threadIdx.x;
    const int lane = tid & 31;
    const int wid = tid >> 5;
    const int rowg = wid >> 1;      // 0..3 : 16-row group
    const int colg = wid & 1;       // 0..1 : chunk-col half / out-col half
    const int bid = blockIdx.x;
    const int t = bid >> 8;         // 256 CTAs per t, adjacent -> weights L2-hot
    const int m0 = (bid & 255) * 64;

    const int rx = lane & 7;
    const int a_row16 = ((lane >> 3) & 1) * 8 + rx;
    const int a_cs = lane >> 4;             // 0/1
    const int b_row16 = ((lane >> 4) & 1) * 8 + rx;
    const int b_cs = (lane >> 3) & 1;       // 0/1

    const uint32_t aoffX = (uint32_t)(rowg * 16 + a_row16) * 256;
    const uint32_t aoffH = (uint32_t)(rowg * 16 + a_row16) * 128;
    const uint32_t boff1 = (uint32_t)(colg * 16 + b_row16) * 256;

    const uint4* w1h = (const uint4*)(g_w1h + (size_t)t * 32768);
    const uint4* w1l = (const uint4*)(g_w1l + (size_t)t * 32768);
    const uint4* w2h = (const uint4*)(g_w2h + (size_t)t * 32768);
    const uint4* w2l = (const uint4*)(g_w2l + (size_t)t * 32768);

    // ---- prologue: X hi/lo + W1(0) + W2(0) via cp.async ----
    {
        const uint4* xh = (const uint4*)(g_xh + ((size_t)t * B_ROWS + m0) * 64);
        const uint4* xl = (const uint4*)(g_xl + ((size_t)t * B_ROWS + m0) * 64);
#pragma unroll
        for (int i = 0; i < 4; i++) {
            int lin = i * TPB + tid;      // 0..1023 : 64 rows x 16 uint4
            int r = lin >> 4, c = lin & 15;
            uint32_t off = (uint32_t)r * 256 + (uint32_t)((c ^ (r & 7)) << 4);
            CP_ASYNC16(sb + SM_XH + off, xh + r * 16 + c);
            CP_ASYNC16(sb + SM_XL + off, xl + r * 16 + c);
        }
        cpa_w1(sb, 0, w1h, w1l, tid);
        cpa_w2(sb, 0, w2h, w2l, tid);
        CP_COMMIT();
        CP_WAIT(0);
        __syncthreads();
    }

    // persistent GEMM2 accumulators: warp = 16 rows x 64 out-cols -> 8 n8-frags
    float c2[8][4];
#pragma unroll
    for (int n = 0; n < 8; n++)
#pragma unroll
        for (int q = 0; q < 4; q++) c2[n][q] = 0.0f;

    const int g = lane >> 2, tt = lane & 3;

    for (int j = 0; j < 16; j++) {
        const uint32_t w1b = sb + SM_W1 + (j & 1) * 16384;
        const uint32_t w2b = sb + SM_W2 + (j & 1) * 16384;

        if (j < 15) {
            cpa_w1(sb, (j + 1) & 1, w1h + (size_t)((j + 1) * 32) * 16,
                   w1l + (size_t)((j + 1) * 32) * 16, tid);
            cpa_w2(sb, (j + 1) & 1, w2h + (size_t)(j + 1) * 4,
                   w2l + (size_t)(j + 1) * 4, tid);
            CP_COMMIT();
        }

        // ---- GEMM1 (fused 3-pass): c1 = Xh*W1h + Xh*W1l + Xl*W1h ----
        // warp tile: 16 rows x 16 chunk-cols -> 2 n8-frags
        float c1[2][4];
#pragma unroll
        for (int n = 0; n < 2; n++)
#pragma unroll
            for (int q = 0; q < 4; q++) c1[n][q] = 0.0f;

#pragma unroll
        for (int k = 0; k < 8; k++) {
            uint32_t asw = (uint32_t)(((2 * k + a_cs) ^ rx) << 4);
            uint32_t bsw = (uint32_t)(((2 * k + b_cs) ^ rx) << 4);
            uint32_t ah[4], al[4], bh[4], bl[4];
            ldsm4(ah, sb + SM_XH + aoffX + asw);
            ldsm4(al, sb + SM_XL + aoffX + asw);
            ldsm4(bh, w1b + boff1 + bsw);
            ldsm4(bl, w1b + 8192 + boff1 + bsw);
            mma_bf16(c1[0], ah, bh[0], bh[1]);
            mma_bf16(c1[0], ah, bl[0], bl[1]);
            mma_bf16(c1[0], al, bh[0], bh[1]);
            mma_bf16(c1[1], ah, bh[2], bh[3]);
            mma_bf16(c1[1], ah, bl[2], bl[3]);
            mma_bf16(c1[1], al, bh[2], bh[3]);
        }

        // ---- GELU + split -> packed H tile (h chunks 0-3 | l chunks 4-7) ----
#pragma unroll
        for (int n = 0; n < 2; n++) {
            int col = colg * 16 + n * 8 + 2 * tt;   // 0..31 chunk k-col
            int ch = col >> 3, cb = (col & 7) * 2;
            int r0 = rowg * 16 + g;
            int r1 = r0 + 8;
            uint32_t hh, ll;
            split2(gelu_f(c1[n][0]), gelu_f(c1[n][1]), hh, ll);
            *(uint32_t*)(smem + SM_H + (uint32_t)r0 * 128 +
                         (uint32_t)((ch ^ (r0 & 7)) << 4) + cb) = hh;
            *(uint32_t*)(smem + SM_H + (uint32_t)r0 * 128 +
                         (uint32_t)(((ch + 4) ^ (r0 & 7)) << 4) + cb) = ll;
            split2(gelu_f(c1[n][2]), gelu_f(c1[n][3]), hh, ll);
            *(uint32_t*)(smem + SM_H + (uint32_t)r1 * 128 +
                         (uint32_t)((ch ^ (r1 & 7)) << 4) + cb) = hh;
            *(uint32_t*)(smem + SM_H + (uint32_t)r1 * 128 +
                         (uint32_t)(((ch + 4) ^ (r1 & 7)) << 4) + cb) = ll;
        }
        __syncthreads();     // H complete

        // ---- GEMM2 (fused 3-pass): c2 += Hh*W2h + Hh*W2l + Hl*W2h ----
#pragma unroll
        for (int k = 0; k < 2; k++) {
            int cha = 2 * k + a_cs;            // 0..3 (h); +4 for l
            int chb = 2 * k + b_cs;
            uint32_t ah[4], al[4];
            ldsm4(ah, sb + SM_H + aoffH + (uint32_t)((cha ^ rx) << 4));
            ldsm4(al, sb + SM_H + aoffH + (uint32_t)(((cha + 4) ^ rx) << 4));
#pragma unroll
            for (int grp = 0; grp < 4; grp++) {
                uint32_t boff = (uint32_t)(colg * 64 + grp * 16 + b_row16) * 128;
                uint32_t bh[4], bl[4];
                ldsm4(bh, w2b + boff + (uint32_t)((chb ^ rx) << 4));
                ldsm4(bl, w2b + boff + (uint32_t)(((chb + 4) ^ rx) << 4));
                mma_bf16(c2[grp * 2], ah, bh[0], bh[1]);
                mma_bf16(c2[grp * 2], ah, bl[0], bl[1]);
                mma_bf16(c2[grp * 2], al, bh[0], bh[1]);
                mma_bf16(c2[grp * 2 + 1], ah, bh[2], bh[3]);
                mma_bf16(c2[grp * 2 + 1], ah, bl[2], bl[3]);
                mma_bf16(c2[grp * 2 + 1], al, bh[2], bh[3]);
            }
        }

        if (j < 15) {
            CP_WAIT(0);
            __syncthreads();   // W(j+1) arrived; H/W readers done
        }
    }

    // ---- store C2 -> g_yp [t][row][128] ----
    {
        float* ybase = g_yp + ((size_t)t * B_ROWS + m0 + rowg * 16) * 128;
#pragma unroll
        for (int n = 0; n < 8; n++) {
            int col = colg * 64 + n * 8 + 2 * tt;
            *(float2*)(ybase + (size_t)g * 128 + col) =
                make_float2(c2[n][0], c2[n][1]);
            *(float2*)(ybase + (size_t)(g + 8) * 128 + col) =
                make_float2(c2[n][2], c2[n][3]);
        }
    }
}

// ---------------- launch ----------------
extern "C" void kernel_launch(void* const* d_in, const int* in_sizes, int n_in,
                              void* d_out, int out_size) {
    const float* x  = (const float*)d_in[0];
    const float* w1 = (const float*)d_in[1];
    const float* w2 = (const float*)d_in[2];
    float* y = (float*)d_out;
    (void)in_sizes; (void)n_in; (void)out_size;

    cudaFuncSetAttribute(ffn_mma_kernel,
                         cudaFuncAttributeMaxDynamicSharedMemorySize, SM_TOTAL);

    permute_x_split<<<B_ROWS, TPB>>>(x);
    permute_w1_split<<<(512 * 64) / TPB, TPB>>>(w1);
    permute_w2_split<<<(128 * 256) / TPB, TPB>>>(w2);
    ffn_mma_kernel<<<TOK * (B_ROWS / 64), TPB, SM_TOTAL>>>();
    permute_y_kernel<<<B_ROWS, TPB>>>(y);
}